// round 1
// baseline (speedup 1.0000x reference)
#include <cuda_runtime.h>
#include <math.h>

#define N_SAMPLES 262144
#define N_K 128
#define N_STEPS 1024
#define K_TILE 8
#define N_TILES (N_K / K_TILE)                    // 16
#define CHUNKS 128
#define SAMPLES_PER_CHUNK (N_SAMPLES / CHUNKS)    // 2048
#define THREADS1 256
#define ITERS (SAMPLES_PER_CHUNK / THREADS1)      // 8
#define VALS 33                                   // 32 accumulators + mask count

// Per-block partial sums: [tile][chunk][33]
__device__ float g_scratch[N_TILES * CHUNKS * VALS];

// ---------------------------------------------------------------------------
// Kernel 1: Fourier reduction.
// Block (chunk, tile): 256 threads, each handles 8 samples for 8 harmonics.
// Per sample: 2 fast sincos, then angle-addition recurrence across the 8
// harmonics in the tile, accumulating tot_s/tot_c/pos_s/pos_c per harmonic.
// ---------------------------------------------------------------------------
__global__ void __launch_bounds__(THREADS1)
reduce_kernel(const float* __restrict__ scores, const unsigned* __restrict__ targets)
{
    const int chunk = blockIdx.x;
    const int tile  = blockIdx.y;
    const int tid   = threadIdx.x;

    float acc[32];
#pragma unroll
    for (int i = 0; i < 32; ++i) acc[i] = 0.f;
    float cnt = 0.f;

    const float TWO_PI = 6.2831855f;             // fl(2*pi), matches reference
    const float k0f = (float)(tile * K_TILE + 1);
    const int base = chunk * SAMPLES_PER_CHUNK + tid;

#pragma unroll
    for (int it = 0; it < ITERS; ++it) {
        const int n = base + it * THREADS1;
        const float sc = scores[n];
        const float m = (targets[n] != 0u) ? 1.f : 0.f;
        cnt += m;

        const float th = TWO_PI * sc;
        float ss, cs;                            // step rotation = (cos th, sin th)
        __sincosf(th, &ss, &cs);
        float s0, c0;                            // start at harmonic k0
        __sincosf(k0f * th, &s0, &c0);

#pragma unroll
        for (int j = 0; j < K_TILE; ++j) {
            acc[j * 4 + 0] += s0;                            // tot sin
            acc[j * 4 + 1] += c0;                            // tot cos
            acc[j * 4 + 2] = fmaf(m, s0, acc[j * 4 + 2]);    // pos sin
            acc[j * 4 + 3] = fmaf(m, c0, acc[j * 4 + 3]);    // pos cos
            // rotate by th: (c,s) -> (c*cs - s*ss, s*cs + c*ss)
            const float ns = fmaf(s0, cs,  c0 * ss);
            const float nc = fmaf(c0, cs, -s0 * ss);
            s0 = ns; c0 = nc;
        }
    }

    // Deterministic block reduction: shuffle within warp, fixed-order across warps.
    __shared__ float red[THREADS1 / 32][VALS];
    const int lane = tid & 31, wid = tid >> 5;
#pragma unroll
    for (int v = 0; v < VALS; ++v) {
        float val = (v < 32) ? acc[v] : cnt;
#pragma unroll
        for (int o = 16; o > 0; o >>= 1)
            val += __shfl_down_sync(0xffffffffu, val, o);
        if (lane == 0) red[wid][v] = val;
    }
    __syncthreads();
    if (tid < VALS) {
        float s = 0.f;
#pragma unroll
        for (int w = 0; w < THREADS1 / 32; ++w) s += red[w][tid];
        g_scratch[(tile * CHUNKS + chunk) * VALS + tid] = s;
    }
}

// ---------------------------------------------------------------------------
// Kernel 2: single block. Reduce scratch -> coefficients -> integrated
// coefficients -> CDF at 1024 thresholds -> AUC scalar.
// ---------------------------------------------------------------------------
__global__ void __launch_bounds__(1024)
finalize_kernel(float* __restrict__ out)
{
    __shared__ float coef[4][N_K];               // 0: tot_s, 1: tot_c, 2: pos_s, 3: pos_c
    __shared__ float isp[N_K], icp[N_K], isn[N_K], icn[N_K];
    __shared__ float posn[N_STEPS + 2], negn[N_STEPS + 2];
    __shared__ float npos_sh;
    __shared__ float redA[32], redB[32];

    const int tid = threadIdx.x;

    // Phase A: sum partials over chunks (fixed order -> deterministic)
    if (tid < 512) {
        const int tile = tid >> 5;
        const int v = tid & 31;
        float s = 0.f;
        for (int c = 0; c < CHUNKS; ++c)
            s += g_scratch[(tile * CHUNKS + c) * VALS + v];
        const int j = v >> 2, q = v & 3;
        coef[q][tile * K_TILE + j] = s;
    } else if (tid == 512) {
        float s = 0.f;
        for (int c = 0; c < CHUNKS; ++c)
            s += g_scratch[c * VALS + 32];       // count only from tile 0
        npos_sh = s;
    }
    __syncthreads();

    // Phase B: normalize coefficients, integrate termwise
    if (tid < N_K) {
        const float EPS = 1.1920929e-7f;
        const float tpk = 6.2831855f * (float)(tid + 1);
        const float npos = npos_sh;
        const float nneg = (float)N_SAMPLES - npos;

        const float ps = (npos < EPS) ? 0.f : coef[2][tid] / fmaxf(npos, EPS);
        const float pc = (npos < EPS) ? 0.f : coef[3][tid] / fmaxf(npos, EPS);
        const float Sneg = coef[0][tid] - coef[2][tid];
        const float Cneg = coef[1][tid] - coef[3][tid];
        const float nsn  = (nneg < EPS) ? 0.f : Sneg / fmaxf(nneg, EPS);
        const float ncn  = (nneg < EPS) ? 0.f : Cneg / fmaxf(nneg, EPS);

        isp[tid] =  pc / tpk;   // int sin coefficient (pos)
        icp[tid] = -ps / tpk;   // int cos coefficient (pos)
        isn[tid] =  ncn / tpk;
        icn[tid] = -nsn / tpk;
    }
    __syncthreads();

    // Phase C: evaluate CDFs at the 1024 thresholds, build normalized arrays
    {
        const float thr = (float)tid / 1023.0f;
        float cdfp = 0.f, cdfn = 0.f;
#pragma unroll 4
        for (int k = 0; k < N_K; ++k) {
            const float tpk = 6.2831855f * (float)(k + 1);
            float s, c;
            __sincosf(thr * tpk, &s, &c);
            cdfp = fmaf(s, isp[k], cdfp);
            cdfp = fmaf(c, icp[k], cdfp);
            cdfn = fmaf(s, isn[k], cdfn);
            cdfn = fmaf(c, icn[k], cdfn);
        }
        posn[tid + 1] = 1.0f - 0.5f * (cdfp + 0.5f);
        negn[tid + 1] = 1.0f - 0.5f * (cdfn + 0.5f);
        if (tid == 0) {
            posn[0] = 1.0f; negn[0] = 1.0f;
            posn[N_STEPS + 1] = 0.0f; negn[N_STEPS + 1] = 0.0f;
        }
    }
    __syncthreads();

    // Phase D: AUC via Riemann sums over 1025 intervals
    float tp = 0.f, tn = 0.f;
    for (int i = tid; i < N_STEPS + 1; i += 1024) {
        tp = fmaf(posn[i], negn[i] - negn[i + 1], tp);   // pos_auc terms
        tn = fmaf(negn[i], posn[i + 1] - posn[i], tn);   // neg_auc terms
    }
    const int lane = tid & 31, wid = tid >> 5;
#pragma unroll
    for (int o = 16; o > 0; o >>= 1) {
        tp += __shfl_down_sync(0xffffffffu, tp, o);
        tn += __shfl_down_sync(0xffffffffu, tn, o);
    }
    if (lane == 0) { redA[wid] = tp; redB[wid] = tn; }
    __syncthreads();
    if (wid == 0) {
        float a = redA[lane], b = redB[lane];
#pragma unroll
        for (int o = 16; o > 0; o >>= 1) {
            a += __shfl_down_sync(0xffffffffu, a, o);
            b += __shfl_down_sync(0xffffffffu, b, o);
        }
        if (lane == 0) {
            const float pos_auc = a;
            const float neg_auc = 1.0f + b;
            out[0] = 0.5f * (pos_auc + neg_auc);
        }
    }
}

extern "C" void kernel_launch(void* const* d_in, const int* in_sizes, int n_in,
                              void* d_out, int out_size)
{
    (void)in_sizes; (void)n_in; (void)out_size;
    const float*    scores  = (const float*)d_in[0];
    const unsigned* targets = (const unsigned*)d_in[1];
    float* out = (float*)d_out;

    dim3 grid(CHUNKS, N_TILES);
    reduce_kernel<<<grid, THREADS1>>>(scores, targets);
    finalize_kernel<<<1, 1024>>>(out);
}

// round 2
// speedup vs baseline: 1.9133x; 1.9133x over previous
#include <cuda_runtime.h>
#include <math.h>

#define N_SAMPLES 262144
#define N_K 128
#define N_STEPS 1024
#define K_TILE 16
#define N_TILES (N_K / K_TILE)                    // 8
#define CHUNKS 256
#define SAMPLES_PER_CHUNK (N_SAMPLES / CHUNKS)    // 1024
#define THREADS1 128
#define ITERS (SAMPLES_PER_CHUNK / THREADS1)      // 8
#define NACC (4 * K_TILE)                         // 64
#define VALS (NACC + 1)                           // 65: 64 accumulators + mask count
#define TWO_PI 6.2831855f

// Per-block partial sums: [tile][chunk][VALS]
__device__ float g_scratch[N_TILES * CHUNKS * VALS];
// Integrated coefficients
__device__ float g_isp[N_K], g_icp[N_K], g_isn[N_K], g_icn[N_K];
// Normalized CDF arrays (1026 entries each)
__device__ float g_posn[N_STEPS + 2], g_negn[N_STEPS + 2];

// ---------------------------------------------------------------------------
// Kernel 1: Fourier reduction via angle-addition recurrence.
// Block (chunk, tile): 128 threads, each handles 8 samples for 16 harmonics.
// ---------------------------------------------------------------------------
__global__ void __launch_bounds__(THREADS1)
reduce_kernel(const float* __restrict__ scores, const unsigned* __restrict__ targets)
{
    const int chunk = blockIdx.x;
    const int tile  = blockIdx.y;
    const int tid   = threadIdx.x;

    float acc[NACC];
#pragma unroll
    for (int i = 0; i < NACC; ++i) acc[i] = 0.f;
    float cnt = 0.f;

    const float k0f = (float)(tile * K_TILE + 1);
    const int base = chunk * SAMPLES_PER_CHUNK + tid;

#pragma unroll
    for (int it = 0; it < ITERS; ++it) {
        const int n = base + it * THREADS1;
        const float sc = scores[n];
        const float m = (targets[n] != 0u) ? 1.f : 0.f;
        cnt += m;

        const float th = TWO_PI * sc;
        float ss, cs;                            // step rotation = (cos th, sin th)
        __sincosf(th, &ss, &cs);
        float s0, c0;                            // start at harmonic k0
        __sincosf(k0f * th, &s0, &c0);

#pragma unroll
        for (int j = 0; j < K_TILE; ++j) {
            acc[j * 4 + 0] += s0;                            // tot sin
            acc[j * 4 + 1] += c0;                            // tot cos
            acc[j * 4 + 2] = fmaf(m, s0, acc[j * 4 + 2]);    // pos sin
            acc[j * 4 + 3] = fmaf(m, c0, acc[j * 4 + 3]);    // pos cos
            // rotate by th: (c,s) -> (c*cs - s*ss, s*cs + c*ss)
            const float ns = fmaf(s0, cs,  c0 * ss);
            const float nc = fmaf(c0, cs, -s0 * ss);
            s0 = ns; c0 = nc;
        }
    }

    // Deterministic block reduction: shuffle within warp, fixed-order across warps.
    __shared__ float red[THREADS1 / 32][VALS];
    const int lane = tid & 31, wid = tid >> 5;
#pragma unroll
    for (int v = 0; v < VALS; ++v) {
        float val = (v < NACC) ? acc[v] : cnt;
#pragma unroll
        for (int o = 16; o > 0; o >>= 1)
            val += __shfl_down_sync(0xffffffffu, val, o);
        if (lane == 0) red[wid][v] = val;
    }
    __syncthreads();
    if (tid < VALS) {
        float s = 0.f;
#pragma unroll
        for (int w = 0; w < THREADS1 / 32; ++w) s += red[w][tid];
        g_scratch[(tile * CHUNKS + chunk) * VALS + tid] = s;
    }
}

// ---------------------------------------------------------------------------
// Kernel 2: per-tile coefficient assembly + normalization + termwise
// integration. Grid = 8 blocks (one per tile), 256 threads.
// ---------------------------------------------------------------------------
__global__ void __launch_bounds__(256)
coef_kernel()
{
    const int tile = blockIdx.x;
    const int t = threadIdx.x;
    const int v = t & 63, g = t >> 6;            // 4 groups of 64 chunks

    __shared__ float part[4][NACC];
    __shared__ float cpart[64];
    __shared__ float coefv[NACC];
    __shared__ float npos_sh;

    // Each thread sums 64 chunks for one value (fixed order -> deterministic)
    {
        float s = 0.f;
        const int cbase = tile * CHUNKS + g * 64;
        for (int c = 0; c < 64; ++c)
            s += g_scratch[(cbase + c) * VALS + v];
        part[g][v] = s;
    }
    // Count partials: threads 0..63 each sum 4 chunks
    if (t < 64) {
        float cc = 0.f;
        const int cbase = tile * CHUNKS + t * 4;
        for (int c = 0; c < 4; ++c)
            cc += g_scratch[(cbase + c) * VALS + NACC];
        cpart[t] = cc;
    }
    __syncthreads();
    if (t == 0) {
        float s2 = 0.f;
        for (int i = 0; i < 64; ++i) s2 += cpart[i];
        npos_sh = s2;
    }
    if (t < NACC)
        coefv[t] = part[0][t] + part[1][t] + part[2][t] + part[3][t];
    __syncthreads();

    if (t < K_TILE) {
        const float EPS = 1.1920929e-7f;
        const int kg = tile * K_TILE + t;
        const float tpk = TWO_PI * (float)(kg + 1);
        const float npos = npos_sh;
        const float nneg = (float)N_SAMPLES - npos;

        const float tot_s = coefv[t * 4 + 0];
        const float tot_c = coefv[t * 4 + 1];
        const float pos_s = coefv[t * 4 + 2];
        const float pos_c = coefv[t * 4 + 3];

        const float ps = (npos < EPS) ? 0.f : pos_s / fmaxf(npos, EPS);
        const float pc = (npos < EPS) ? 0.f : pos_c / fmaxf(npos, EPS);
        const float nsn = (nneg < EPS) ? 0.f : (tot_s - pos_s) / fmaxf(nneg, EPS);
        const float ncn = (nneg < EPS) ? 0.f : (tot_c - pos_c) / fmaxf(nneg, EPS);

        g_isp[kg] =  pc / tpk;    // int-sin coefficient (pos)
        g_icp[kg] = -ps / tpk;    // int-cos coefficient (pos)
        g_isn[kg] =  ncn / tpk;
        g_icn[kg] = -nsn / tpk;
    }
}

// ---------------------------------------------------------------------------
// Kernel 3: CDF evaluation at 1024 thresholds. One warp per step.
// Grid = 32 blocks x 1024 threads (32 warps each).
// ---------------------------------------------------------------------------
__global__ void __launch_bounds__(1024)
cdf_kernel()
{
    const int step = blockIdx.x * 32 + (threadIdx.x >> 5);
    const int lane = threadIdx.x & 31;
    const float thr = (float)step / 1023.0f;

    float cdfp = 0.f, cdfn = 0.f;
#pragma unroll
    for (int i = 0; i < 4; ++i) {
        const int k = lane + i * 32;
        const float tpk = TWO_PI * (float)(k + 1);
        float s, c;
        __sincosf(thr * tpk, &s, &c);
        cdfp = fmaf(s, g_isp[k], fmaf(c, g_icp[k], cdfp));
        cdfn = fmaf(s, g_isn[k], fmaf(c, g_icn[k], cdfn));
    }
#pragma unroll
    for (int o = 16; o > 0; o >>= 1) {
        cdfp += __shfl_down_sync(0xffffffffu, cdfp, o);
        cdfn += __shfl_down_sync(0xffffffffu, cdfn, o);
    }
    if (lane == 0) {
        g_posn[step + 1] = 1.0f - 0.5f * (cdfp + 0.5f);
        g_negn[step + 1] = 1.0f - 0.5f * (cdfn + 0.5f);
        if (step == 0) {
            g_posn[0] = 1.0f; g_negn[0] = 1.0f;
            g_posn[N_STEPS + 1] = 0.0f; g_negn[N_STEPS + 1] = 0.0f;
        }
    }
}

// ---------------------------------------------------------------------------
// Kernel 4: AUC via Riemann sums over 1025 intervals. One block.
// ---------------------------------------------------------------------------
__global__ void __launch_bounds__(1024)
auc_kernel(float* __restrict__ out)
{
    const int tid = threadIdx.x;
    __shared__ float redA[32], redB[32];

    float tp = 0.f, tn = 0.f;
    for (int i = tid; i < N_STEPS + 1; i += 1024) {
        const float p0 = g_posn[i], p1 = g_posn[i + 1];
        const float q0 = g_negn[i], q1 = g_negn[i + 1];
        tp = fmaf(p0, q0 - q1, tp);   // pos_auc terms
        tn = fmaf(q0, p1 - p0, tn);   // neg_auc terms
    }
    const int lane = tid & 31, wid = tid >> 5;
#pragma unroll
    for (int o = 16; o > 0; o >>= 1) {
        tp += __shfl_down_sync(0xffffffffu, tp, o);
        tn += __shfl_down_sync(0xffffffffu, tn, o);
    }
    if (lane == 0) { redA[wid] = tp; redB[wid] = tn; }
    __syncthreads();
    if (wid == 0) {
        float a = redA[lane], b = redB[lane];
#pragma unroll
        for (int o = 16; o > 0; o >>= 1) {
            a += __shfl_down_sync(0xffffffffu, a, o);
            b += __shfl_down_sync(0xffffffffu, b, o);
        }
        if (lane == 0)
            out[0] = 0.5f * (a + (1.0f + b));
    }
}

extern "C" void kernel_launch(void* const* d_in, const int* in_sizes, int n_in,
                              void* d_out, int out_size)
{
    (void)in_sizes; (void)n_in; (void)out_size;
    const float*    scores  = (const float*)d_in[0];
    const unsigned* targets = (const unsigned*)d_in[1];
    float* out = (float*)d_out;

    dim3 grid(CHUNKS, N_TILES);
    reduce_kernel<<<grid, THREADS1>>>(scores, targets);
    coef_kernel<<<N_TILES, 256>>>();
    cdf_kernel<<<32, 1024>>>();
    auc_kernel<<<1, 1024>>>(out);
}

// round 3
// speedup vs baseline: 2.0554x; 1.0743x over previous
#include <cuda_runtime.h>
#include <math.h>

#define N_SAMPLES 262144
#define N_K 128
#define N_STEPS 1024
#define K_TILE 16
#define NPAIR (K_TILE / 2)                        // 8 packed harmonic pairs
#define N_TILES (N_K / K_TILE)                    // 8
#define CHUNKS 64
#define SAMPLES_PER_CHUNK (N_SAMPLES / CHUNKS)    // 4096
#define THREADS1 256
#define ITERS (SAMPLES_PER_CHUNK / THREADS1)      // 16
#define NACC (4 * K_TILE)                         // 64
#define VALS (NACC + 1)                           // 65
#define TWO_PI 6.2831855f

typedef unsigned long long u64;

// Packed f32x2 helpers (FFMA2 path — only reachable via PTX)
__device__ __forceinline__ u64 pk(float lo, float hi) {
    u64 r; asm("mov.b64 %0, {%1, %2};" : "=l"(r) : "f"(lo), "f"(hi)); return r;
}
__device__ __forceinline__ void upk(u64 v, float& lo, float& hi) {
    asm("mov.b64 {%0, %1}, %2;" : "=f"(lo), "=f"(hi) : "l"(v));
}
__device__ __forceinline__ u64 f2fma(u64 a, u64 b, u64 c) {
    u64 d; asm("fma.rn.f32x2 %0, %1, %2, %3;" : "=l"(d) : "l"(a), "l"(b), "l"(c)); return d;
}
__device__ __forceinline__ u64 f2add(u64 a, u64 b) {
    u64 d; asm("add.rn.f32x2 %0, %1, %2;" : "=l"(d) : "l"(a), "l"(b)); return d;
}
__device__ __forceinline__ u64 f2mul(u64 a, u64 b) {
    u64 d; asm("mul.rn.f32x2 %0, %1, %2;" : "=l"(d) : "l"(a), "l"(b)); return d;
}

// Per-block partial sums: [tile][chunk][VALS]
__device__ float g_scratch[N_TILES * CHUNKS * VALS];
// Normalized CDF arrays (1026 entries each)
__device__ float g_posn[N_STEPS + 2], g_negn[N_STEPS + 2];
// Self-resetting completion counter for the fused finalize kernel
__device__ unsigned int g_sync = 0;

// ---------------------------------------------------------------------------
// Kernel 1: Fourier reduction via packed-f32x2 angle-addition recurrence.
// Block (chunk, tile): 256 threads, 16 samples each, 16 harmonics (8 pairs).
// Pair p holds harmonics (k0+2p, k0+2p+1); rotation step is 2*theta.
// ---------------------------------------------------------------------------
__global__ void __launch_bounds__(THREADS1)
reduce_kernel(const float* __restrict__ scores, const unsigned* __restrict__ targets)
{
    const int chunk = blockIdx.x;
    const int tile  = blockIdx.y;
    const int tid   = threadIdx.x;

    u64 accTS[NPAIR], accTC[NPAIR], accPS[NPAIR], accPC[NPAIR];
#pragma unroll
    for (int p = 0; p < NPAIR; ++p) { accTS[p] = 0; accTC[p] = 0; accPS[p] = 0; accPC[p] = 0; }
    float cnt = 0.f;

    const float k0f = (float)(tile * K_TILE + 1);
    const int base = chunk * SAMPLES_PER_CHUNK + tid;

#pragma unroll 2
    for (int it = 0; it < ITERS; ++it) {
        const int n = base + it * THREADS1;
        const float sc = scores[n];
        const float m = (targets[n] != 0u) ? 1.f : 0.f;
        cnt += m;

        const float th = TWO_PI * sc;
        float s1, c1;
        __sincosf(th, &s1, &c1);
        float sA, cA;                              // harmonic k0
        __sincosf(k0f * th, &sA, &cA);
        // harmonic k0+1 = rotate (sA,cA) by th
        const float sB = fmaf(sA, c1,  cA * s1);
        const float cB = fmaf(cA, c1, -sA * s1);
        // double angle: rotation step 2*th
        const float s2 = 2.f * s1 * c1;
        const float c2 = fmaf(c1, c1, -s1 * s1);

        u64 sp  = pk(sA, sB);
        u64 cp  = pk(cA, cB);
        const u64 c2p  = pk(c2, c2);
        const u64 s2p  = pk(s2, s2);
        const u64 ns2p = pk(-s2, -s2);
        const u64 mp   = pk(m, m);

#pragma unroll
        for (int p = 0; p < NPAIR; ++p) {
            accTS[p] = f2add(accTS[p], sp);
            accTC[p] = f2add(accTC[p], cp);
            accPS[p] = f2fma(mp, sp, accPS[p]);
            accPC[p] = f2fma(mp, cp, accPC[p]);
            const u64 t1 = f2mul(cp, s2p);
            const u64 t2 = f2mul(sp, ns2p);
            const u64 nsp = f2fma(sp, c2p, t1);
            const u64 ncp = f2fma(cp, c2p, t2);
            sp = nsp; cp = ncp;
        }
    }

    // Unpack into the canonical v = j*4+q layout
    float vals[VALS];
#pragma unroll
    for (int p = 0; p < NPAIR; ++p) {
        float lo, hi;
        upk(accTS[p], lo, hi); vals[(2*p)*4 + 0] = lo; vals[(2*p+1)*4 + 0] = hi;
        upk(accTC[p], lo, hi); vals[(2*p)*4 + 1] = lo; vals[(2*p+1)*4 + 1] = hi;
        upk(accPS[p], lo, hi); vals[(2*p)*4 + 2] = lo; vals[(2*p+1)*4 + 2] = hi;
        upk(accPC[p], lo, hi); vals[(2*p)*4 + 3] = lo; vals[(2*p+1)*4 + 3] = hi;
    }
    vals[NACC] = cnt;

    // Deterministic block reduction
    __shared__ float red[THREADS1 / 32][VALS];
    const int lane = tid & 31, wid = tid >> 5;
#pragma unroll
    for (int v = 0; v < VALS; ++v) {
        float val = vals[v];
#pragma unroll
        for (int o = 16; o > 0; o >>= 1)
            val += __shfl_down_sync(0xffffffffu, val, o);
        if (lane == 0) red[wid][v] = val;
    }
    __syncthreads();
    if (tid < VALS) {
        float s = 0.f;
#pragma unroll
        for (int w = 0; w < THREADS1 / 32; ++w) s += red[w][tid];
        g_scratch[(tile * CHUNKS + chunk) * VALS + tid] = s;
    }
}

// ---------------------------------------------------------------------------
// Kernel 2 (fused finalize): 32 blocks x 1024 threads.
// Phase A: each block redundantly assembles coefficients (fixed order ->
//          deterministic and identical across blocks).
// Phase B: block b evaluates CDF steps [b*32, b*32+32) (one warp per step).
// Phase C: last block to finish computes the AUC scalar and resets counter.
// ---------------------------------------------------------------------------
__global__ void __launch_bounds__(1024)
finalize_kernel(float* __restrict__ out)
{
    const int t = threadIdx.x;

    __shared__ float sp2[2 * N_TILES * VALS];     // 1040 half-sums
    __shared__ float scoef[N_TILES * VALS];       // 520
    __shared__ float sisp[N_K], sicp[N_K], sisn[N_K], sicn[N_K];

    // Phase A1: half-sums over 32 chunks each
    if (t < 2 * N_TILES * VALS) {
        const int v520 = t >> 1, h = t & 1;
        const int tile = v520 / VALS, v = v520 % VALS;
        const float* base = &g_scratch[(tile * CHUNKS + h * 32) * VALS + v];
        float s = 0.f;
#pragma unroll 8
        for (int c = 0; c < 32; ++c) s += base[c * VALS];
        sp2[t] = s;
    }
    __syncthreads();
    if (t < N_TILES * VALS) scoef[t] = sp2[2 * t] + sp2[2 * t + 1];
    __syncthreads();

    // Phase A2: normalize + integrate -> per-harmonic coefficients
    if (t < N_K) {
        const float EPS = 1.1920929e-7f;
        const int tile = t / K_TILE, j = t % K_TILE;
        const float tpk = TWO_PI * (float)(t + 1);
        const float npos = scoef[64];             // tile 0, v = 64 (count)
        const float nneg = (float)N_SAMPLES - npos;

        const float tot_s = scoef[tile * VALS + j * 4 + 0];
        const float tot_c = scoef[tile * VALS + j * 4 + 1];
        const float pos_s = scoef[tile * VALS + j * 4 + 2];
        const float pos_c = scoef[tile * VALS + j * 4 + 3];

        const float ps  = (npos < EPS) ? 0.f : pos_s / fmaxf(npos, EPS);
        const float pc  = (npos < EPS) ? 0.f : pos_c / fmaxf(npos, EPS);
        const float nsn = (nneg < EPS) ? 0.f : (tot_s - pos_s) / fmaxf(nneg, EPS);
        const float ncn = (nneg < EPS) ? 0.f : (tot_c - pos_c) / fmaxf(nneg, EPS);

        sisp[t] =  pc / tpk;
        sicp[t] = -ps / tpk;
        sisn[t] =  ncn / tpk;
        sicn[t] = -nsn / tpk;
    }
    __syncthreads();

    // Phase B: CDF evaluation, one warp per threshold step
    {
        const int w = t >> 5, lane = t & 31;
        const int step = blockIdx.x * 32 + w;
        const float thr = (float)step / 1023.0f;

        float cdfp = 0.f, cdfn = 0.f;
#pragma unroll
        for (int i = 0; i < 4; ++i) {
            const int k = lane + i * 32;
            const float tpk = TWO_PI * (float)(k + 1);
            float s, c;
            __sincosf(thr * tpk, &s, &c);
            cdfp = fmaf(s, sisp[k], fmaf(c, sicp[k], cdfp));
            cdfn = fmaf(s, sisn[k], fmaf(c, sicn[k], cdfn));
        }
#pragma unroll
        for (int o = 16; o > 0; o >>= 1) {
            cdfp += __shfl_down_sync(0xffffffffu, cdfp, o);
            cdfn += __shfl_down_sync(0xffffffffu, cdfn, o);
        }
        if (lane == 0) {
            g_posn[step + 1] = 1.0f - 0.5f * (cdfp + 0.5f);
            g_negn[step + 1] = 1.0f - 0.5f * (cdfn + 0.5f);
            if (step == 0) {
                g_posn[0] = 1.0f; g_negn[0] = 1.0f;
                g_posn[N_STEPS + 1] = 0.0f; g_negn[N_STEPS + 1] = 0.0f;
            }
        }
    }

    // Phase C: last block computes AUC
    __threadfence();
    __syncthreads();
    __shared__ unsigned int is_last;
    if (t == 0) {
        const unsigned int old = atomicAdd(&g_sync, 1u);
        is_last = (old == 31u) ? 1u : 0u;
    }
    __syncthreads();
    if (!is_last) return;
    __threadfence();                              // acquire side

    __shared__ float redA[32], redB[32];
    float tp = 0.f, tn = 0.f;
    for (int i = t; i < N_STEPS + 1; i += 1024) {
        const float p0 = g_posn[i], p1 = g_posn[i + 1];
        const float q0 = g_negn[i], q1 = g_negn[i + 1];
        tp = fmaf(p0, q0 - q1, tp);
        tn = fmaf(q0, p1 - p0, tn);
    }
    const int lane = t & 31, wid = t >> 5;
#pragma unroll
    for (int o = 16; o > 0; o >>= 1) {
        tp += __shfl_down_sync(0xffffffffu, tp, o);
        tn += __shfl_down_sync(0xffffffffu, tn, o);
    }
    if (lane == 0) { redA[wid] = tp; redB[wid] = tn; }
    __syncthreads();
    if (wid == 0) {
        float a = redA[lane], b = redB[lane];
#pragma unroll
        for (int o = 16; o > 0; o >>= 1) {
            a += __shfl_down_sync(0xffffffffu, a, o);
            b += __shfl_down_sync(0xffffffffu, b, o);
        }
        if (lane == 0) {
            out[0] = 0.5f * (a + (1.0f + b));
            g_sync = 0;                           // self-reset for graph replay
        }
    }
}

extern "C" void kernel_launch(void* const* d_in, const int* in_sizes, int n_in,
                              void* d_out, int out_size)
{
    (void)in_sizes; (void)n_in; (void)out_size;
    const float*    scores  = (const float*)d_in[0];
    const unsigned* targets = (const unsigned*)d_in[1];
    float* out = (float*)d_out;

    dim3 grid(CHUNKS, N_TILES);
    reduce_kernel<<<grid, THREADS1>>>(scores, targets);
    finalize_kernel<<<32, 1024>>>(out);
}

// round 4
// speedup vs baseline: 2.0924x; 1.0180x over previous
#include <cuda_runtime.h>
#include <math.h>

#define N_SAMPLES 262144
#define N_FLOAT4 (N_SAMPLES / 4)                  // 65536
#define N_K 128
#define N_STEPS 1024
#define K_TILE 32
#define NPAIR (K_TILE / 2)                        // 16 packed harmonic pairs
#define N_TILES (N_K / K_TILE)                    // 4
#define CHUNKS 37                                 // 37*4 = 148 blocks = #SMs
#define THREADS1 256
#define NACC (4 * K_TILE)                         // 128
#define VALS (NACC + 1)                           // 129
#define TWO_PI 6.2831855f

typedef unsigned long long u64;

// Packed f32x2 helpers (FFMA2 path — only reachable via PTX)
__device__ __forceinline__ u64 pk(float lo, float hi) {
    u64 r; asm("mov.b64 %0, {%1, %2};" : "=l"(r) : "f"(lo), "f"(hi)); return r;
}
__device__ __forceinline__ void upk(u64 v, float& lo, float& hi) {
    asm("mov.b64 {%0, %1}, %2;" : "=f"(lo), "=f"(hi) : "l"(v));
}
__device__ __forceinline__ u64 f2fma(u64 a, u64 b, u64 c) {
    u64 d; asm("fma.rn.f32x2 %0, %1, %2, %3;" : "=l"(d) : "l"(a), "l"(b), "l"(c)); return d;
}
__device__ __forceinline__ u64 f2add(u64 a, u64 b) {
    u64 d; asm("add.rn.f32x2 %0, %1, %2;" : "=l"(d) : "l"(a), "l"(b)); return d;
}
__device__ __forceinline__ u64 f2mul(u64 a, u64 b) {
    u64 d; asm("mul.rn.f32x2 %0, %1, %2;" : "=l"(d) : "l"(a), "l"(b)); return d;
}

// Per-block partial sums: [tile][chunk][VALS]
__device__ float g_scratch[N_TILES * CHUNKS * VALS];
// Per-tile reduced coefficients: [tile][VALS]
__device__ float g_coef[N_TILES * VALS];
// Normalized CDF arrays
__device__ float g_posn[N_STEPS + 2], g_negn[N_STEPS + 2];
// Self-resetting counters
__device__ unsigned int g_tilecnt[N_TILES] = {0, 0, 0, 0};
__device__ unsigned int g_sync = 0;

// ---------------------------------------------------------------------------
// Kernel 1: Fourier reduction, packed-f32x2 angle-addition recurrence.
// Grid (37 chunks, 4 tiles) = 148 blocks (one per SM), 256 threads.
// Pair p holds harmonics (k0+2p, k0+2p+1); rotation step is 2*theta.
// Last block per tile also folds chunk partials into g_coef.
// ---------------------------------------------------------------------------
__global__ void __launch_bounds__(THREADS1)
reduce_kernel(const float4* __restrict__ scores4, const uint4* __restrict__ targets4)
{
    const int chunk = blockIdx.x;
    const int tile  = blockIdx.y;
    const int tid   = threadIdx.x;

    u64 accTS[NPAIR], accTC[NPAIR], accPS[NPAIR], accPC[NPAIR];
#pragma unroll
    for (int p = 0; p < NPAIR; ++p) { accTS[p] = 0; accTC[p] = 0; accPS[p] = 0; accPC[p] = 0; }
    float cnt = 0.f;

    const float k0f = (float)(tile * K_TILE + 1);
    const int start4 = (chunk * N_FLOAT4) / CHUNKS;
    const int end4   = ((chunk + 1) * N_FLOAT4) / CHUNKS;

    for (int i = start4 + tid; i < end4; i += THREADS1) {
        const float4 sv = scores4[i];
        const uint4  tv = targets4[i];
        const float scs[4] = {sv.x, sv.y, sv.z, sv.w};
        const float msk[4] = {tv.x ? 1.f : 0.f, tv.y ? 1.f : 0.f,
                              tv.z ? 1.f : 0.f, tv.w ? 1.f : 0.f};
#pragma unroll
        for (int e = 0; e < 4; ++e) {
            const float sc = scs[e];
            const float m  = msk[e];
            cnt += m;

            const float th = TWO_PI * sc;
            float s1, c1;
            __sincosf(th, &s1, &c1);
            float sA, cA;                          // harmonic k0
            __sincosf(k0f * th, &sA, &cA);
            const float sB = fmaf(sA, c1,  cA * s1);   // harmonic k0+1
            const float cB = fmaf(cA, c1, -sA * s1);
            const float s2 = 2.f * s1 * c1;            // rotation step 2*theta
            const float c2 = fmaf(c1, c1, -s1 * s1);

            u64 sp = pk(sA, sB);
            u64 cp = pk(cA, cB);
            const u64 c2p  = pk(c2, c2);
            const u64 s2p  = pk(s2, s2);
            const u64 ns2p = pk(-s2, -s2);
            const u64 mp   = pk(m, m);

#pragma unroll
            for (int p = 0; p < NPAIR; ++p) {
                accTS[p] = f2add(accTS[p], sp);
                accTC[p] = f2add(accTC[p], cp);
                accPS[p] = f2fma(mp, sp, accPS[p]);
                accPC[p] = f2fma(mp, cp, accPC[p]);
                const u64 t1  = f2mul(cp, s2p);
                const u64 t2  = f2mul(sp, ns2p);
                const u64 nsp = f2fma(sp, c2p, t1);
                const u64 ncp = f2fma(cp, c2p, t2);
                sp = nsp; cp = ncp;
            }
        }
    }

    // Warp reduction directly on packed u64 accumulators (f2add + 64-bit shfl)
    __shared__ float red[THREADS1 / 32][VALS];
    const int lane = tid & 31, wid = tid >> 5;

#pragma unroll
    for (int p = 0; p < NPAIR; ++p) {
        u64 a0 = accTS[p], a1 = accTC[p], a2 = accPS[p], a3 = accPC[p];
#pragma unroll
        for (int o = 16; o > 0; o >>= 1) {
            a0 = f2add(a0, __shfl_down_sync(0xffffffffu, a0, o));
            a1 = f2add(a1, __shfl_down_sync(0xffffffffu, a1, o));
            a2 = f2add(a2, __shfl_down_sync(0xffffffffu, a2, o));
            a3 = f2add(a3, __shfl_down_sync(0xffffffffu, a3, o));
        }
        if (lane == 0) {
            float lo, hi;
            upk(a0, lo, hi); red[wid][(2*p)*4 + 0] = lo; red[wid][(2*p+1)*4 + 0] = hi;
            upk(a1, lo, hi); red[wid][(2*p)*4 + 1] = lo; red[wid][(2*p+1)*4 + 1] = hi;
            upk(a2, lo, hi); red[wid][(2*p)*4 + 2] = lo; red[wid][(2*p+1)*4 + 2] = hi;
            upk(a3, lo, hi); red[wid][(2*p)*4 + 3] = lo; red[wid][(2*p+1)*4 + 3] = hi;
        }
    }
    {
        float v = cnt;
#pragma unroll
        for (int o = 16; o > 0; o >>= 1)
            v += __shfl_down_sync(0xffffffffu, v, o);
        if (lane == 0) red[wid][NACC] = v;
    }
    __syncthreads();

    if (tid < VALS) {
        float s = 0.f;
#pragma unroll
        for (int w = 0; w < THREADS1 / 32; ++w) s += red[w][tid];
        g_scratch[(tile * CHUNKS + chunk) * VALS + tid] = s;
    }

    // Tail: last block of this tile folds chunk partials into g_coef
    __threadfence();
    __syncthreads();
    __shared__ unsigned int is_last;
    if (tid == 0) {
        const unsigned int old = atomicAdd(&g_tilecnt[tile], 1u);
        is_last = (old == CHUNKS - 1) ? 1u : 0u;
    }
    __syncthreads();
    if (!is_last) return;
    __threadfence();

    if (tid < VALS) {
        float s = 0.f;
        const float* base = &g_scratch[tile * CHUNKS * VALS + tid];
#pragma unroll 8
        for (int c = 0; c < CHUNKS; ++c) s += base[c * VALS];
        g_coef[tile * VALS + tid] = s;
    }
    if (tid == 0) g_tilecnt[tile] = 0;            // self-reset for graph replay
}

// ---------------------------------------------------------------------------
// Kernel 2 (finalize): 32 blocks x 1024 threads.
// Each block reads the tiny g_coef, builds integrated coefficients, evaluates
// its 32 CDF steps (one warp per step); last block computes the AUC scalar.
// ---------------------------------------------------------------------------
__global__ void __launch_bounds__(1024)
finalize_kernel(float* __restrict__ out)
{
    const int t = threadIdx.x;
    __shared__ float sisp[N_K], sicp[N_K], sisn[N_K], sicn[N_K];

    if (t < N_K) {
        const float EPS = 1.1920929e-7f;
        const int tile = t / K_TILE, j = t % K_TILE;
        const float tpk = TWO_PI * (float)(t + 1);
        const float npos = g_coef[NACC];          // tile 0 count = total positives
        const float nneg = (float)N_SAMPLES - npos;

        const float tot_s = g_coef[tile * VALS + j * 4 + 0];
        const float tot_c = g_coef[tile * VALS + j * 4 + 1];
        const float pos_s = g_coef[tile * VALS + j * 4 + 2];
        const float pos_c = g_coef[tile * VALS + j * 4 + 3];

        const float ps  = (npos < EPS) ? 0.f : pos_s / fmaxf(npos, EPS);
        const float pc  = (npos < EPS) ? 0.f : pos_c / fmaxf(npos, EPS);
        const float nsn = (nneg < EPS) ? 0.f : (tot_s - pos_s) / fmaxf(nneg, EPS);
        const float ncn = (nneg < EPS) ? 0.f : (tot_c - pos_c) / fmaxf(nneg, EPS);

        sisp[t] =  pc / tpk;
        sicp[t] = -ps / tpk;
        sisn[t] =  ncn / tpk;
        sicn[t] = -nsn / tpk;
    }
    __syncthreads();

    // CDF: one warp per threshold step
    {
        const int w = t >> 5, lane = t & 31;
        const int step = blockIdx.x * 32 + w;
        const float thr = (float)step / 1023.0f;

        float cdfp = 0.f, cdfn = 0.f;
#pragma unroll
        for (int i = 0; i < 4; ++i) {
            const int k = lane + i * 32;
            const float tpk = TWO_PI * (float)(k + 1);
            float s, c;
            __sincosf(thr * tpk, &s, &c);
            cdfp = fmaf(s, sisp[k], fmaf(c, sicp[k], cdfp));
            cdfn = fmaf(s, sisn[k], fmaf(c, sicn[k], cdfn));
        }
#pragma unroll
        for (int o = 16; o > 0; o >>= 1) {
            cdfp += __shfl_down_sync(0xffffffffu, cdfp, o);
            cdfn += __shfl_down_sync(0xffffffffu, cdfn, o);
        }
        if (lane == 0) {
            g_posn[step + 1] = 1.0f - 0.5f * (cdfp + 0.5f);
            g_negn[step + 1] = 1.0f - 0.5f * (cdfn + 0.5f);
            if (step == 0) {
                g_posn[0] = 1.0f; g_negn[0] = 1.0f;
                g_posn[N_STEPS + 1] = 0.0f; g_negn[N_STEPS + 1] = 0.0f;
            }
        }
    }

    // Last block computes AUC
    __threadfence();
    __syncthreads();
    __shared__ unsigned int is_last;
    if (t == 0) {
        const unsigned int old = atomicAdd(&g_sync, 1u);
        is_last = (old == 31u) ? 1u : 0u;
    }
    __syncthreads();
    if (!is_last) return;
    __threadfence();

    __shared__ float redA[32], redB[32];
    float tp = 0.f, tn = 0.f;
    for (int i = t; i < N_STEPS + 1; i += 1024) {
        const float p0 = g_posn[i], p1 = g_posn[i + 1];
        const float q0 = g_negn[i], q1 = g_negn[i + 1];
        tp = fmaf(p0, q0 - q1, tp);
        tn = fmaf(q0, p1 - p0, tn);
    }
    const int lane = t & 31, wid = t >> 5;
#pragma unroll
    for (int o = 16; o > 0; o >>= 1) {
        tp += __shfl_down_sync(0xffffffffu, tp, o);
        tn += __shfl_down_sync(0xffffffffu, tn, o);
    }
    if (lane == 0) { redA[wid] = tp; redB[wid] = tn; }
    __syncthreads();
    if (wid == 0) {
        float a = redA[lane], b = redB[lane];
#pragma unroll
        for (int o = 16; o > 0; o >>= 1) {
            a += __shfl_down_sync(0xffffffffu, a, o);
            b += __shfl_down_sync(0xffffffffu, b, o);
        }
        if (lane == 0) {
            out[0] = 0.5f * (a + (1.0f + b));
            g_sync = 0;                           // self-reset for graph replay
        }
    }
}

extern "C" void kernel_launch(void* const* d_in, const int* in_sizes, int n_in,
                              void* d_out, int out_size)
{
    (void)in_sizes; (void)n_in; (void)out_size;
    const float4* scores4  = (const float4*)d_in[0];
    const uint4*  targets4 = (const uint4*)d_in[1];
    float* out = (float*)d_out;

    dim3 grid(CHUNKS, N_TILES);
    reduce_kernel<<<grid, THREADS1>>>(scores4, targets4);
    finalize_kernel<<<32, 1024>>>(out);
}